// round 11
// baseline (speedup 1.0000x reference)
#include <cuda_runtime.h>
#include <cuda_bf16.h>
#include <math.h>
#include <stdint.h>

// ---------------- problem constants ----------------
#define DIMC   192
#define HEADS  6
#define HD     32
#define NTOK   49
#define BW     4096
#define HIDDEN 768
#define ROWS   (BW * NTOK)   // 200704

// ---------------- scratch (device globals) ----------------
__device__ __nv_bfloat16 g_xln_h[(size_t)ROWS * DIMC];
__device__ __nv_bfloat16 g_xln_l[(size_t)ROWS * DIMC];
__device__ float         g_qkv [(size_t)ROWS * 3 * DIMC];
__device__ __nv_bfloat16 g_att_h[(size_t)ROWS * DIMC];
__device__ __nv_bfloat16 g_att_l[(size_t)ROWS * DIMC];
__device__ float         g_x2  [(size_t)ROWS * DIMC];
__device__ __nv_bfloat16 g_hid_h[(size_t)ROWS * HIDDEN];
__device__ __nv_bfloat16 g_hid_l[(size_t)ROWS * HIDDEN];
// transposed weights [N][K], hi/lo
__device__ __nv_bfloat16 g_wqkv_h[576 * 192], g_wqkv_l[576 * 192];
__device__ __nv_bfloat16 g_wproj_h[192 * 192], g_wproj_l[192 * 192];
__device__ __nv_bfloat16 g_wfc1_h[768 * 192], g_wfc1_l[768 * 192];
__device__ __nv_bfloat16 g_wfc2_h[192 * 768], g_wfc2_l[192 * 768];

// ---------------- helpers ----------------
__device__ __forceinline__ uint32_t smem_u32(const void* p) {
    uint32_t a;
    asm("{ .reg .u64 t; cvta.to.shared.u64 t, %1; cvt.u32.u64 %0, t; }" : "=r"(a) : "l"(p));
    return a;
}
__device__ __forceinline__ uint32_t lds32(uint32_t a) {
    uint32_t v;
    asm volatile("ld.shared.b32 %0, [%1];" : "=r"(v) : "r"(a));
    return v;
}
#define CP16(sm, gp) asm volatile("cp.async.cg.shared.global [%0], [%1], 16;" :: "r"(sm), "l"(gp) : "memory")
#define CP_COMMIT()  asm volatile("cp.async.commit_group;" ::: "memory")
#define CP_WAIT1()   asm volatile("cp.async.wait_group 1;" ::: "memory")
#define CP_WAIT0()   asm volatile("cp.async.wait_group 0;" ::: "memory")
#define SWZ(x) ((x) ^ (((x) >> 3) & 0x70))

__device__ __forceinline__ void mma_bf16(float c[4],
    uint32_t a0, uint32_t a1, uint32_t a2, uint32_t a3, uint32_t b0, uint32_t b1)
{
    asm volatile(
        "mma.sync.aligned.m16n8k16.row.col.f32.bf16.bf16.f32 "
        "{%0,%1,%2,%3}, {%4,%5,%6,%7}, {%8,%9}, {%0,%1,%2,%3};"
        : "+f"(c[0]), "+f"(c[1]), "+f"(c[2]), "+f"(c[3])
        : "r"(a0), "r"(a1), "r"(a2), "r"(a3), "r"(b0), "r"(b1));
}

__device__ __forceinline__ void bf16split(float x, __nv_bfloat16& h, __nv_bfloat16& l)
{
    h = __float2bfloat16(x);
    l = __float2bfloat16(x - __bfloat162float(h));
}
__device__ __forceinline__ float gelu_exact(float v)
{
    return 0.5f * v * (1.f + erff(v * 0.70710678118654752440f));
}

// ---------------- weight convert + transpose: w[K][N] f32 -> hi/lo [N][K] bf16 ----------------
__global__ void wconv(const float* __restrict__ w, __nv_bfloat16* __restrict__ hi,
                      __nv_bfloat16* __restrict__ lo, int K, int N)
{
    int idx = blockIdx.x * 256 + threadIdx.x;
    if (idx >= K * N) return;
    int k = idx / N, n = idx - k * N;
    __nv_bfloat16 h, l;
    bf16split(w[idx], h, l);
    hi[(size_t)n * K + k] = h;
    lo[(size_t)n * K + k] = l;
}

// ---------------- LayerNorm -> hi/lo bf16 ----------------
__global__ void ln_kernel(const float* __restrict__ x,
                          const float* __restrict__ g,
                          const float* __restrict__ b,
                          __nv_bfloat16* __restrict__ yh,
                          __nv_bfloat16* __restrict__ yl)
{
    int warp = (blockIdx.x * blockDim.x + threadIdx.x) >> 5;
    int lane = threadIdx.x & 31;
    if (warp >= ROWS) return;
    const float* xr = x + (size_t)warp * DIMC;
    float v[6];
    float s = 0.f, sq = 0.f;
#pragma unroll
    for (int i = 0; i < 6; i++) {
        v[i] = xr[lane + 32 * i];
        s += v[i]; sq += v[i] * v[i];
    }
#pragma unroll
    for (int o = 16; o > 0; o >>= 1) {
        s  += __shfl_xor_sync(0xffffffffu, s,  o);
        sq += __shfl_xor_sync(0xffffffffu, sq, o);
    }
    float mu = s * (1.f / DIMC);
    float var = sq * (1.f / DIMC) - mu * mu;
    float rs = rsqrtf(var + 1e-5f);
#pragma unroll
    for (int i = 0; i < 6; i++) {
        int c = lane + 32 * i;
        float y = (v[i] - mu) * rs * g[c] + b[c];
        __nv_bfloat16 h, l;
        bf16split(y, h, l);
        yh[(size_t)warp * DIMC + c] = h;
        yl[(size_t)warp * DIMC + c] = l;
    }
}

// ---------------- tensor-core GEMM (mma.sync bf16 hi/lo split) ----------------
// C[M,N] = A[M,K] @ Bw[N,K]^T.  Block: 64(M) x 192(N), BK=32, 256 threads, 2 CTA/SM.
// smem rows pack [hi 64B | lo 64B] -> 128B rows, SW128 swizzle.
#define EPI_BIAS  1
#define EPI_RESID 2
#define EPI_GELU  4
#define EPI_SPLIT 8

#define SA_OFF 0
#define SB_OFF 8192          // A: 64 rows * 128B
#define BUFSZ  32768         // + B: 192 rows * 128B = 24576
#define SMEM_G (2 * BUFSZ)   // 65536

template <int EPI>
__global__ void __launch_bounds__(256, 2)
tc_gemm(const __nv_bfloat16* __restrict__ Ah, const __nv_bfloat16* __restrict__ Al,
        const __nv_bfloat16* __restrict__ Bh, const __nv_bfloat16* __restrict__ Bl,
        const float* __restrict__ bias, const float* __restrict__ resid,
        float* __restrict__ Cf, __nv_bfloat16* __restrict__ Ch, __nv_bfloat16* __restrict__ Cl,
        int M, int N, int K)
{
    extern __shared__ char smem[];
    uint32_t sb = smem_u32(smem);
    int tid  = threadIdx.x;
    int wid  = tid >> 5, lane = tid & 31;
    int g    = lane >> 2, t = lane & 3;
    int wm   = wid & 1;          // 2 warps along M: rows wm*32
    int wn   = wid >> 1;         // 4 warps along N: cols wn*48
    int mBase = blockIdx.y * 64;
    int nBase = blockIdx.x * 192;

    // A copy mapping: 64 rows * 8 chunks(16B) = 512; 2 per thread
    int a_row = tid >> 2;            // 0..63
    int a_c0  = (tid & 3) * 2;       // chunk {0..7}: 0-3 = hi, 4-7 = lo

    float acc[2][6][4];
#pragma unroll
    for (int i = 0; i < 2; i++)
#pragma unroll
        for (int j = 0; j < 6; j++)
#pragma unroll
            for (int k2 = 0; k2 < 4; k2++) acc[i][j][k2] = 0.f;

    int chunks = K / 32;

    auto issue_copy = [&](int ck) {
        uint32_t bo = sb + (uint32_t)(ck & 1) * BUFSZ;
        int kB = ck * 32;
        // A: row-packed hi|lo
#pragma unroll
        for (int i = 0; i < 2; i++) {
            int c = a_c0 + i;
            uint32_t so = SWZ((uint32_t)(a_row * 128 + c * 16));
            const __nv_bfloat16* src = (c < 4)
                ? Ah + (size_t)(mBase + a_row) * K + kB + c * 8
                : Al + (size_t)(mBase + a_row) * K + kB + (c - 4) * 8;
            CP16(bo + SA_OFF + so, src);
        }
        // B: 192 rows * 8 chunks = 1536; 6 per thread
#pragma unroll
        for (int i = 0; i < 6; i++) {
            int idx = tid + 256 * i;
            int br = idx >> 3, c = idx & 7;
            uint32_t so = SWZ((uint32_t)(br * 128 + c * 16));
            const __nv_bfloat16* src = (c < 4)
                ? Bh + (size_t)(nBase + br) * K + kB + c * 8
                : Bl + (size_t)(nBase + br) * K + kB + (c - 4) * 8;
            CP16(bo + SB_OFF + so, src);
        }
        CP_COMMIT();
    };

    issue_copy(0);
    for (int ck = 0; ck < chunks; ck++) {
        if (ck + 1 < chunks) { issue_copy(ck + 1); CP_WAIT1(); }
        else                 { CP_WAIT0(); }
        __syncthreads();

        uint32_t bo = sb + (uint32_t)(ck & 1) * BUFSZ;
        uint32_t pA = bo + SA_OFF, pB = bo + SB_OFF;

#pragma unroll
        for (int ks = 0; ks < 2; ks++) {
            uint32_t ah[2][4], al[2][4];
#pragma unroll
            for (int mt = 0; mt < 2; mt++) {
                int r0 = wm * 32 + mt * 16 + g;
                uint32_t base0 = (uint32_t)(r0 * 128 + ks * 32 + t * 4);
                uint32_t base1 = (uint32_t)((r0 + 8) * 128 + ks * 32 + t * 4);
                ah[mt][0] = lds32(pA + SWZ(base0));
                ah[mt][1] = lds32(pA + SWZ(base1));
                ah[mt][2] = lds32(pA + SWZ(base0 + 16));
                ah[mt][3] = lds32(pA + SWZ(base1 + 16));
                al[mt][0] = lds32(pA + SWZ(base0 + 64));
                al[mt][1] = lds32(pA + SWZ(base1 + 64));
                al[mt][2] = lds32(pA + SWZ(base0 + 80));
                al[mt][3] = lds32(pA + SWZ(base1 + 80));
            }
#pragma unroll
            for (int nt = 0; nt < 6; nt++) {
                int rn = wn * 48 + nt * 8 + g;
                uint32_t baseb = (uint32_t)(rn * 128 + ks * 32 + t * 4);
                uint32_t bh0 = lds32(pB + SWZ(baseb));
                uint32_t bh1 = lds32(pB + SWZ(baseb + 16));
                uint32_t bl0 = lds32(pB + SWZ(baseb + 64));
                uint32_t bl1 = lds32(pB + SWZ(baseb + 80));
#pragma unroll
                for (int mt = 0; mt < 2; mt++) {
                    mma_bf16(acc[mt][nt], ah[mt][0], ah[mt][1], ah[mt][2], ah[mt][3], bh0, bh1);
                    mma_bf16(acc[mt][nt], ah[mt][0], ah[mt][1], ah[mt][2], ah[mt][3], bl0, bl1);
                    mma_bf16(acc[mt][nt], al[mt][0], al[mt][1], al[mt][2], al[mt][3], bh0, bh1);
                }
            }
        }
        __syncthreads();
    }

    // ---- epilogue ----
#pragma unroll
    for (int mt = 0; mt < 2; mt++) {
#pragma unroll
        for (int nt = 0; nt < 6; nt++) {
            int col = nBase + wn * 48 + nt * 8 + t * 2;
            float b0 = 0.f, b1 = 0.f;
            if (EPI & EPI_BIAS) { b0 = bias[col]; b1 = bias[col + 1]; }
#pragma unroll
            for (int h = 0; h < 2; h++) {
                size_t row = (size_t)(mBase + wm * 32 + mt * 16 + g + h * 8);
                size_t off = row * N + col;
                float v0 = acc[mt][nt][h * 2 + 0] + b0;
                float v1 = acc[mt][nt][h * 2 + 1] + b1;
                if (EPI & EPI_GELU) { v0 = gelu_exact(v0); v1 = gelu_exact(v1); }
                if (EPI & EPI_RESID) {
                    float2 r = *(const float2*)(resid + off);
                    v0 += r.x; v1 += r.y;
                }
                if (EPI & EPI_SPLIT) {
                    __nv_bfloat16 h0, l0, h1, l1;
                    bf16split(v0, h0, l0);
                    bf16split(v1, h1, l1);
                    __nv_bfloat162 hh, ll;
                    hh.x = h0; hh.y = h1;
                    ll.x = l0; ll.y = l1;
                    *(__nv_bfloat162*)(Ch + off) = hh;
                    *(__nv_bfloat162*)(Cl + off) = ll;
                } else {
                    float2 o; o.x = v0; o.y = v1;
                    *(float2*)(Cf + off) = o;
                }
            }
        }
    }
}

// ---------------- windowed attention ----------------
__global__ __launch_bounds__(128)
void attn_kernel(const float* __restrict__ qkv,
                 const float* __restrict__ bias_table,
                 const int* __restrict__ rel_index,
                 __nv_bfloat16* __restrict__ out_h,
                 __nv_bfloat16* __restrict__ out_l)
{
    __shared__ float qs[NTOK * HD];
    __shared__ float ks[HD * 50];
    __shared__ float vs[NTOK * HD];
    __shared__ float bsm[NTOK * NTOK];
    __shared__ float sc[NTOK * 50];

    int b = blockIdx.x;
    int h = blockIdx.y;
    int tid = threadIdx.x;
    const float scale = 0.17677669529663688110f;

    for (int idx = tid; idx < NTOK * HD; idx += 128) {
        int t = idx >> 5, d = idx & 31;
        size_t base = ((size_t)(b * NTOK + t)) * (3 * DIMC) + h * HD + d;
        qs[t * HD + d] = qkv[base] * scale;
        ks[d * 50 + t] = qkv[base + DIMC];
        vs[t * HD + d] = qkv[base + 2 * DIMC];
    }
    for (int idx = tid; idx < NTOK * NTOK; idx += 128)
        bsm[idx] = bias_table[rel_index[idx] * HEADS + h];
    __syncthreads();

    for (int idx = tid; idx < NTOK * NTOK; idx += 128) {
        int i = idx / NTOK, j = idx - i * NTOK;
        float s = 0.f;
#pragma unroll
        for (int d = 0; d < HD; d++) s = fmaf(qs[i * HD + d], ks[d * 50 + j], s);
        sc[i * 50 + j] = s + bsm[idx];
    }
    __syncthreads();

    if (tid < NTOK) {
        float mx = -1e30f;
#pragma unroll 7
        for (int j = 0; j < NTOK; j++) mx = fmaxf(mx, sc[tid * 50 + j]);
        float sum = 0.f;
#pragma unroll 7
        for (int j = 0; j < NTOK; j++) {
            float e = expf(sc[tid * 50 + j] - mx);
            sc[tid * 50 + j] = e;
            sum += e;
        }
        float inv = 1.f / sum;
#pragma unroll 7
        for (int j = 0; j < NTOK; j++) sc[tid * 50 + j] *= inv;
    }
    __syncthreads();

    for (int idx = tid; idx < NTOK * HD; idx += 128) {
        int t = idx >> 5, d = idx & 31;
        float s = 0.f;
#pragma unroll 7
        for (int j = 0; j < NTOK; j++) s = fmaf(sc[t * 50 + j], vs[j * HD + d], s);
        size_t off = ((size_t)(b * NTOK + t)) * DIMC + h * HD + d;
        __nv_bfloat16 hh, ll;
        bf16split(s, hh, ll);
        out_h[off] = hh;
        out_l[off] = ll;
    }
}

// ---------------- launch ----------------
extern "C" void kernel_launch(void* const* d_in, const int* in_sizes, int n_in,
                              void* d_out, int out_size)
{
    const float* x       = (const float*)d_in[0];
    const float* ln1_g   = (const float*)d_in[1];
    const float* ln1_b   = (const float*)d_in[2];
    const float* qkv_w   = (const float*)d_in[3];
    const float* proj_w  = (const float*)d_in[4];
    const float* proj_b  = (const float*)d_in[5];
    const float* btab    = (const float*)d_in[6];
    const float* ln2_g   = (const float*)d_in[7];
    const float* ln2_b   = (const float*)d_in[8];
    const float* fc1_w   = (const float*)d_in[9];
    const float* fc1_b   = (const float*)d_in[10];
    const float* fc2_w   = (const float*)d_in[11];
    const float* fc2_b   = (const float*)d_in[12];
    const int*   relidx  = (const int*)d_in[13];
    float* out = (float*)d_out;

    __nv_bfloat16 *xln_h, *xln_l, *att_h, *att_l, *hid_h, *hid_l;
    __nv_bfloat16 *wqkv_h, *wqkv_l, *wproj_h, *wproj_l, *wfc1_h, *wfc1_l, *wfc2_h, *wfc2_l;
    float *qkv, *x2;
    cudaGetSymbolAddress((void**)&xln_h, g_xln_h);
    cudaGetSymbolAddress((void**)&xln_l, g_xln_l);
    cudaGetSymbolAddress((void**)&qkv,   g_qkv);
    cudaGetSymbolAddress((void**)&att_h, g_att_h);
    cudaGetSymbolAddress((void**)&att_l, g_att_l);
    cudaGetSymbolAddress((void**)&x2,    g_x2);
    cudaGetSymbolAddress((void**)&hid_h, g_hid_h);
    cudaGetSymbolAddress((void**)&hid_l, g_hid_l);
    cudaGetSymbolAddress((void**)&wqkv_h, g_wqkv_h);
    cudaGetSymbolAddress((void**)&wqkv_l, g_wqkv_l);
    cudaGetSymbolAddress((void**)&wproj_h, g_wproj_h);
    cudaGetSymbolAddress((void**)&wproj_l, g_wproj_l);
    cudaGetSymbolAddress((void**)&wfc1_h, g_wfc1_h);
    cudaGetSymbolAddress((void**)&wfc1_l, g_wfc1_l);
    cudaGetSymbolAddress((void**)&wfc2_h, g_wfc2_h);
    cudaGetSymbolAddress((void**)&wfc2_l, g_wfc2_l);

    cudaFuncSetAttribute(tc_gemm<0>, cudaFuncAttributeMaxDynamicSharedMemorySize, SMEM_G);
    cudaFuncSetAttribute(tc_gemm<EPI_BIAS | EPI_RESID>, cudaFuncAttributeMaxDynamicSharedMemorySize, SMEM_G);
    cudaFuncSetAttribute(tc_gemm<EPI_BIAS | EPI_GELU | EPI_SPLIT>, cudaFuncAttributeMaxDynamicSharedMemorySize, SMEM_G);

    // 0) weight conversion (transpose + hi/lo split)
    wconv<<<(192 * 576 + 255) / 256, 256>>>(qkv_w,  wqkv_h,  wqkv_l,  192, 576);
    wconv<<<(192 * 192 + 255) / 256, 256>>>(proj_w, wproj_h, wproj_l, 192, 192);
    wconv<<<(192 * 768 + 255) / 256, 256>>>(fc1_w,  wfc1_h,  wfc1_l,  192, 768);
    wconv<<<(768 * 192 + 255) / 256, 256>>>(fc2_w,  wfc2_h,  wfc2_l,  768, 192);

    // 1) LN1 -> hi/lo
    ln_kernel<<<ROWS / 8, 256>>>(x, ln1_g, ln1_b, xln_h, xln_l);
    // 2) QKV: (ROWS,192) x (192,576) -> f32
    tc_gemm<0><<<dim3(3, ROWS / 64), 256, SMEM_G>>>(
        xln_h, xln_l, wqkv_h, wqkv_l, nullptr, nullptr, qkv, nullptr, nullptr, ROWS, 576, 192);
    // 3) attention -> hi/lo
    attn_kernel<<<dim3(BW, HEADS), 128>>>(qkv, btab, relidx, att_h, att_l);
    // 4) proj + bias + residual(x) -> x2 (f32)
    tc_gemm<EPI_BIAS | EPI_RESID><<<dim3(1, ROWS / 64), 256, SMEM_G>>>(
        att_h, att_l, wproj_h, wproj_l, proj_b, x, x2, nullptr, nullptr, ROWS, 192, 192);
    // 5) LN2 -> hi/lo
    ln_kernel<<<ROWS / 8, 256>>>(x2, ln2_g, ln2_b, xln_h, xln_l);
    // 6) fc1 + bias + gelu -> hid (hi/lo bf16)
    tc_gemm<EPI_BIAS | EPI_GELU | EPI_SPLIT><<<dim3(4, ROWS / 64), 256, SMEM_G>>>(
        xln_h, xln_l, wfc1_h, wfc1_l, fc1_b, nullptr, nullptr, hid_h, hid_l, ROWS, HIDDEN, 192);
    // 7) fc2 + bias + residual(x2) -> out (f32)
    tc_gemm<EPI_BIAS | EPI_RESID><<<dim3(1, ROWS / 64), 256, SMEM_G>>>(
        hid_h, hid_l, wfc2_h, wfc2_l, fc2_b, x2, out, nullptr, nullptr, ROWS, 192, HIDDEN);
}

// round 16
// speedup vs baseline: 1.1823x; 1.1823x over previous
#include <cuda_runtime.h>
#include <cuda_bf16.h>
#include <math.h>
#include <stdint.h>

// ---------------- problem constants ----------------
#define DIMC   192
#define HEADS  6
#define HD     32
#define NTOK   49
#define BW     4096
#define HIDDEN 768
#define ROWS   (BW * NTOK)   // 200704

// ---------------- scratch (device globals) ----------------
__device__ __nv_bfloat16 g_xln_h[(size_t)ROWS * DIMC];
__device__ __nv_bfloat16 g_xln_l[(size_t)ROWS * DIMC];
__device__ float         g_qkv [(size_t)ROWS * 3 * DIMC];
__device__ __nv_bfloat16 g_att_h[(size_t)ROWS * DIMC];
__device__ __nv_bfloat16 g_att_l[(size_t)ROWS * DIMC];
__device__ float         g_x2  [(size_t)ROWS * DIMC];
__device__ __nv_bfloat16 g_hid_h[(size_t)ROWS * HIDDEN];
__device__ __nv_bfloat16 g_hid_l[(size_t)ROWS * HIDDEN];
// transposed weights [N][K], hi/lo
__device__ __nv_bfloat16 g_wqkv_h[576 * 192], g_wqkv_l[576 * 192];
__device__ __nv_bfloat16 g_wproj_h[192 * 192], g_wproj_l[192 * 192];
__device__ __nv_bfloat16 g_wfc1_h[768 * 192], g_wfc1_l[768 * 192];
__device__ __nv_bfloat16 g_wfc2_h[192 * 768], g_wfc2_l[192 * 768];

// ---------------- helpers ----------------
__device__ __forceinline__ uint32_t smem_u32(const void* p) {
    uint32_t a;
    asm("{ .reg .u64 t; cvta.to.shared.u64 t, %1; cvt.u32.u64 %0, t; }" : "=r"(a) : "l"(p));
    return a;
}
__device__ __forceinline__ uint32_t lds32(uint32_t a) {
    uint32_t v;
    asm volatile("ld.shared.b32 %0, [%1];" : "=r"(v) : "r"(a));
    return v;
}
#define CP16(sm, gp) asm volatile("cp.async.cg.shared.global [%0], [%1], 16;" :: "r"(sm), "l"(gp) : "memory")
#define CP_COMMIT()  asm volatile("cp.async.commit_group;" ::: "memory")
#define CP_WAIT1()   asm volatile("cp.async.wait_group 1;" ::: "memory")
#define CP_WAIT0()   asm volatile("cp.async.wait_group 0;" ::: "memory")
#define SWZ(x) ((x) ^ (((x) >> 3) & 0x70))

__device__ __forceinline__ void mma_bf16(float c[4],
    uint32_t a0, uint32_t a1, uint32_t a2, uint32_t a3, uint32_t b0, uint32_t b1)
{
    asm volatile(
        "mma.sync.aligned.m16n8k16.row.col.f32.bf16.bf16.f32 "
        "{%0,%1,%2,%3}, {%4,%5,%6,%7}, {%8,%9}, {%0,%1,%2,%3};"
        : "+f"(c[0]), "+f"(c[1]), "+f"(c[2]), "+f"(c[3])
        : "r"(a0), "r"(a1), "r"(a2), "r"(a3), "r"(b0), "r"(b1));
}

__device__ __forceinline__ void bf16split(float x, __nv_bfloat16& h, __nv_bfloat16& l)
{
    h = __float2bfloat16(x);
    l = __float2bfloat16(x - __bfloat162float(h));
}
__device__ __forceinline__ float gelu_exact(float v)
{
    return 0.5f * v * (1.f + erff(v * 0.70710678118654752440f));
}

// ---------------- weight convert + transpose: w[K][N] f32 -> hi/lo [N][K] bf16 ----------------
__global__ void wconv(const float* __restrict__ w, __nv_bfloat16* __restrict__ hi,
                      __nv_bfloat16* __restrict__ lo, int K, int N)
{
    int idx = blockIdx.x * 256 + threadIdx.x;
    if (idx >= K * N) return;
    int k = idx / N, n = idx - k * N;
    __nv_bfloat16 h, l;
    bf16split(w[idx], h, l);
    hi[(size_t)n * K + k] = h;
    lo[(size_t)n * K + k] = l;
}

// ---------------- LayerNorm -> hi/lo bf16 ----------------
__global__ void ln_kernel(const float* __restrict__ x,
                          const float* __restrict__ g,
                          const float* __restrict__ b,
                          __nv_bfloat16* __restrict__ yh,
                          __nv_bfloat16* __restrict__ yl)
{
    int warp = (blockIdx.x * blockDim.x + threadIdx.x) >> 5;
    int lane = threadIdx.x & 31;
    if (warp >= ROWS) return;
    const float* xr = x + (size_t)warp * DIMC;
    float v[6];
    float s = 0.f, sq = 0.f;
#pragma unroll
    for (int i = 0; i < 6; i++) {
        v[i] = xr[lane + 32 * i];
        s += v[i]; sq += v[i] * v[i];
    }
#pragma unroll
    for (int o = 16; o > 0; o >>= 1) {
        s  += __shfl_xor_sync(0xffffffffu, s,  o);
        sq += __shfl_xor_sync(0xffffffffu, sq, o);
    }
    float mu = s * (1.f / DIMC);
    float var = sq * (1.f / DIMC) - mu * mu;
    float rs = rsqrtf(var + 1e-5f);
#pragma unroll
    for (int i = 0; i < 6; i++) {
        int c = lane + 32 * i;
        float y = (v[i] - mu) * rs * g[c] + b[c];
        __nv_bfloat16 h, l;
        bf16split(y, h, l);
        yh[(size_t)warp * DIMC + c] = h;
        yl[(size_t)warp * DIMC + c] = l;
    }
}

// ---------------- tensor-core GEMM (mma.sync bf16 hi/lo split) ----------------
// C[M,N] = A[M,K] @ Bw[N,K]^T. Block: 128(M) x 192(N), BK=64, 256 threads,
// warp tile 64x48 (2 M-warp-groups x 4 N-warp-groups -> B redundancy 2).
#define EPI_BIAS  1
#define EPI_RESID 2
#define EPI_GELU  4
#define EPI_SPLIT 8

#define SA_H 0
#define SA_L 16384
#define SB_H 32768
#define SB_L 57344
#define BUFSZ 81920
#define SMEM_G (2 * BUFSZ)   // 163840

template <int EPI>
__global__ void __launch_bounds__(256, 1)
tc_gemm(const __nv_bfloat16* __restrict__ Ah, const __nv_bfloat16* __restrict__ Al,
        const __nv_bfloat16* __restrict__ Bh, const __nv_bfloat16* __restrict__ Bl,
        const float* __restrict__ bias, const float* __restrict__ resid,
        float* __restrict__ Cf, __nv_bfloat16* __restrict__ Ch, __nv_bfloat16* __restrict__ Cl,
        int M, int N, int K)
{
    extern __shared__ char smem[];
    uint32_t sb = smem_u32(smem);
    int tid  = threadIdx.x;
    int wid  = tid >> 5, lane = tid & 31;
    int g    = lane >> 2, t = lane & 3;
    int wm   = wid & 1;          // 2 warps along M: rows wm*64
    int wn   = wid >> 1;         // 4 warps along N: cols wn*48
    int mBase = blockIdx.y * 128;
    int nBase = blockIdx.x * 192;

    // copy mapping: A 128 rows * 8 chunks = 1024 per region; 4 per thread
    int a_row = tid >> 1;            // 0..127
    int a_ch0 = (tid & 1) * 4;       // chunks {0..3} or {4..7}

    float acc[4][6][4];
#pragma unroll
    for (int i = 0; i < 4; i++)
#pragma unroll
        for (int j = 0; j < 6; j++)
#pragma unroll
            for (int k2 = 0; k2 < 4; k2++) acc[i][j][k2] = 0.f;

    int chunks = K / 64;

    auto issue_copy = [&](int ck) {
        uint32_t bo = sb + (uint32_t)(ck & 1) * BUFSZ;
        int kB = ck * 64;
        const __nv_bfloat16* gAh = Ah + (size_t)(mBase + a_row) * K + kB;
        const __nv_bfloat16* gAl = Al + (size_t)(mBase + a_row) * K + kB;
#pragma unroll
        for (int i = 0; i < 4; i++) {
            int ch = a_ch0 + i;
            uint32_t so = SWZ((uint32_t)(a_row * 128 + ch * 16));
            CP16(bo + SA_H + so, gAh + ch * 8);
            CP16(bo + SA_L + so, gAl + ch * 8);
        }
#pragma unroll
        for (int i = 0; i < 6; i++) {
            int idx = tid + 256 * i;          // < 1536 = 192 rows * 8 chunks
            int br = idx >> 3, bch = idx & 7;
            uint32_t so = SWZ((uint32_t)(br * 128 + bch * 16));
            const __nv_bfloat16* gBh = Bh + (size_t)(nBase + br) * K + kB + bch * 8;
            const __nv_bfloat16* gBl = Bl + (size_t)(nBase + br) * K + kB + bch * 8;
            CP16(bo + SB_H + so, gBh);
            CP16(bo + SB_L + so, gBl);
        }
        CP_COMMIT();
    };

    issue_copy(0);
    for (int ck = 0; ck < chunks; ck++) {
        if (ck + 1 < chunks) { issue_copy(ck + 1); CP_WAIT1(); }
        else                 { CP_WAIT0(); }
        __syncthreads();

        uint32_t bo = sb + (uint32_t)(ck & 1) * BUFSZ;
        uint32_t pAh = bo + SA_H, pAl = bo + SA_L;
        uint32_t pBh = bo + SB_H, pBl = bo + SB_L;

#pragma unroll
        for (int ks = 0; ks < 4; ks++) {
            uint32_t ah[4][4], al[4][4];
#pragma unroll
            for (int mt = 0; mt < 4; mt++) {
                int r0 = wm * 64 + mt * 16 + g;
                uint32_t o0 = SWZ((uint32_t)(r0 * 128 + ks * 32 + t * 4));
                uint32_t o1 = SWZ((uint32_t)((r0 + 8) * 128 + ks * 32 + t * 4));
                uint32_t o2 = SWZ((uint32_t)(r0 * 128 + ks * 32 + t * 4 + 16));
                uint32_t o3 = SWZ((uint32_t)((r0 + 8) * 128 + ks * 32 + t * 4 + 16));
                ah[mt][0] = lds32(pAh + o0); ah[mt][1] = lds32(pAh + o1);
                ah[mt][2] = lds32(pAh + o2); ah[mt][3] = lds32(pAh + o3);
                al[mt][0] = lds32(pAl + o0); al[mt][1] = lds32(pAl + o1);
                al[mt][2] = lds32(pAl + o2); al[mt][3] = lds32(pAl + o3);
            }
#pragma unroll
            for (int nt = 0; nt < 6; nt++) {
                int rn = wn * 48 + nt * 8 + g;
                uint32_t ob0 = SWZ((uint32_t)(rn * 128 + ks * 32 + t * 4));
                uint32_t ob1 = SWZ((uint32_t)(rn * 128 + ks * 32 + t * 4 + 16));
                uint32_t bh0 = lds32(pBh + ob0), bh1 = lds32(pBh + ob1);
                uint32_t bl0 = lds32(pBl + ob0), bl1 = lds32(pBl + ob1);
#pragma unroll
                for (int mt = 0; mt < 4; mt++) {
                    mma_bf16(acc[mt][nt], ah[mt][0], ah[mt][1], ah[mt][2], ah[mt][3], bh0, bh1);
                    mma_bf16(acc[mt][nt], ah[mt][0], ah[mt][1], ah[mt][2], ah[mt][3], bl0, bl1);
                    mma_bf16(acc[mt][nt], al[mt][0], al[mt][1], al[mt][2], al[mt][3], bh0, bh1);
                }
            }
        }
        __syncthreads();
    }

    // ---- epilogue ----
#pragma unroll
    for (int mt = 0; mt < 4; mt++) {
#pragma unroll
        for (int nt = 0; nt < 6; nt++) {
            int col = nBase + wn * 48 + nt * 8 + t * 2;
            float b0 = 0.f, b1 = 0.f;
            if (EPI & EPI_BIAS) { b0 = bias[col]; b1 = bias[col + 1]; }
#pragma unroll
            for (int h = 0; h < 2; h++) {
                size_t row = (size_t)(mBase + wm * 64 + mt * 16 + g + h * 8);
                size_t off = row * N + col;
                float v0 = acc[mt][nt][h * 2 + 0] + b0;
                float v1 = acc[mt][nt][h * 2 + 1] + b1;
                if (EPI & EPI_GELU) { v0 = gelu_exact(v0); v1 = gelu_exact(v1); }
                if (EPI & EPI_RESID) {
                    float2 r = *(const float2*)(resid + off);
                    v0 += r.x; v1 += r.y;
                }
                if (EPI & EPI_SPLIT) {
                    __nv_bfloat16 h0, l0, h1, l1;
                    bf16split(v0, h0, l0);
                    bf16split(v1, h1, l1);
                    __nv_bfloat162 hh, ll;
                    hh.x = h0; hh.y = h1;
                    ll.x = l0; ll.y = l1;
                    *(__nv_bfloat162*)(Ch + off) = hh;
                    *(__nv_bfloat162*)(Cl + off) = ll;
                } else {
                    float2 o; o.x = v0; o.y = v1;
                    *(float2*)(Cf + off) = o;
                }
            }
        }
    }
}

// ---------------- windowed attention ----------------
__global__ __launch_bounds__(128)
void attn_kernel(const float* __restrict__ qkv,
                 const float* __restrict__ bias_table,
                 const int* __restrict__ rel_index,
                 __nv_bfloat16* __restrict__ out_h,
                 __nv_bfloat16* __restrict__ out_l)
{
    __shared__ float qs[NTOK * HD];
    __shared__ float ks[HD * 50];
    __shared__ float vs[NTOK * HD];
    __shared__ float bsm[NTOK * NTOK];
    __shared__ float sc[NTOK * 50];

    int b = blockIdx.x;
    int h = blockIdx.y;
    int tid = threadIdx.x;
    const float scale = 0.17677669529663688110f;

    for (int idx = tid; idx < NTOK * HD; idx += 128) {
        int t = idx >> 5, d = idx & 31;
        size_t base = ((size_t)(b * NTOK + t)) * (3 * DIMC) + h * HD + d;
        qs[t * HD + d] = qkv[base] * scale;
        ks[d * 50 + t] = qkv[base + DIMC];
        vs[t * HD + d] = qkv[base + 2 * DIMC];
    }
    for (int idx = tid; idx < NTOK * NTOK; idx += 128)
        bsm[idx] = bias_table[rel_index[idx] * HEADS + h];
    __syncthreads();

    for (int idx = tid; idx < NTOK * NTOK; idx += 128) {
        int i = idx / NTOK, j = idx - i * NTOK;
        float s = 0.f;
#pragma unroll
        for (int d = 0; d < HD; d++) s = fmaf(qs[i * HD + d], ks[d * 50 + j], s);
        sc[i * 50 + j] = s + bsm[idx];
    }
    __syncthreads();

    if (tid < NTOK) {
        float mx = -1e30f;
#pragma unroll 7
        for (int j = 0; j < NTOK; j++) mx = fmaxf(mx, sc[tid * 50 + j]);
        float sum = 0.f;
#pragma unroll 7
        for (int j = 0; j < NTOK; j++) {
            float e = expf(sc[tid * 50 + j] - mx);
            sc[tid * 50 + j] = e;
            sum += e;
        }
        float inv = 1.f / sum;
#pragma unroll 7
        for (int j = 0; j < NTOK; j++) sc[tid * 50 + j] *= inv;
    }
    __syncthreads();

    for (int idx = tid; idx < NTOK * HD; idx += 128) {
        int t = idx >> 5, d = idx & 31;
        float s = 0.f;
#pragma unroll 7
        for (int j = 0; j < NTOK; j++) s = fmaf(sc[t * 50 + j], vs[j * HD + d], s);
        size_t off = ((size_t)(b * NTOK + t)) * DIMC + h * HD + d;
        __nv_bfloat16 hh, ll;
        bf16split(s, hh, ll);
        out_h[off] = hh;
        out_l[off] = ll;
    }
}

// ---------------- launch ----------------
extern "C" void kernel_launch(void* const* d_in, const int* in_sizes, int n_in,
                              void* d_out, int out_size)
{
    const float* x       = (const float*)d_in[0];
    const float* ln1_g   = (const float*)d_in[1];
    const float* ln1_b   = (const float*)d_in[2];
    const float* qkv_w   = (const float*)d_in[3];
    const float* proj_w  = (const float*)d_in[4];
    const float* proj_b  = (const float*)d_in[5];
    const float* btab    = (const float*)d_in[6];
    const float* ln2_g   = (const float*)d_in[7];
    const float* ln2_b   = (const float*)d_in[8];
    const float* fc1_w   = (const float*)d_in[9];
    const float* fc1_b   = (const float*)d_in[10];
    const float* fc2_w   = (const float*)d_in[11];
    const float* fc2_b   = (const float*)d_in[12];
    const int*   relidx  = (const int*)d_in[13];
    float* out = (float*)d_out;

    __nv_bfloat16 *xln_h, *xln_l, *att_h, *att_l, *hid_h, *hid_l;
    __nv_bfloat16 *wqkv_h, *wqkv_l, *wproj_h, *wproj_l, *wfc1_h, *wfc1_l, *wfc2_h, *wfc2_l;
    float *qkv, *x2;
    cudaGetSymbolAddress((void**)&xln_h, g_xln_h);
    cudaGetSymbolAddress((void**)&xln_l, g_xln_l);
    cudaGetSymbolAddress((void**)&qkv,   g_qkv);
    cudaGetSymbolAddress((void**)&att_h, g_att_h);
    cudaGetSymbolAddress((void**)&att_l, g_att_l);
    cudaGetSymbolAddress((void**)&x2,    g_x2);
    cudaGetSymbolAddress((void**)&hid_h, g_hid_h);
    cudaGetSymbolAddress((void**)&hid_l, g_hid_l);
    cudaGetSymbolAddress((void**)&wqkv_h, g_wqkv_h);
    cudaGetSymbolAddress((void**)&wqkv_l, g_wqkv_l);
    cudaGetSymbolAddress((void**)&wproj_h, g_wproj_h);
    cudaGetSymbolAddress((void**)&wproj_l, g_wproj_l);
    cudaGetSymbolAddress((void**)&wfc1_h, g_wfc1_h);
    cudaGetSymbolAddress((void**)&wfc1_l, g_wfc1_l);
    cudaGetSymbolAddress((void**)&wfc2_h, g_wfc2_h);
    cudaGetSymbolAddress((void**)&wfc2_l, g_wfc2_l);

    cudaFuncSetAttribute(tc_gemm<0>, cudaFuncAttributeMaxDynamicSharedMemorySize, SMEM_G);
    cudaFuncSetAttribute(tc_gemm<EPI_BIAS | EPI_RESID>, cudaFuncAttributeMaxDynamicSharedMemorySize, SMEM_G);
    cudaFuncSetAttribute(tc_gemm<EPI_BIAS | EPI_GELU | EPI_SPLIT>, cudaFuncAttributeMaxDynamicSharedMemorySize, SMEM_G);

    // 0) weight conversion (transpose + hi/lo split)
    wconv<<<(192 * 576 + 255) / 256, 256>>>(qkv_w,  wqkv_h,  wqkv_l,  192, 576);
    wconv<<<(192 * 192 + 255) / 256, 256>>>(proj_w, wproj_h, wproj_l, 192, 192);
    wconv<<<(192 * 768 + 255) / 256, 256>>>(fc1_w,  wfc1_h,  wfc1_l,  192, 768);
    wconv<<<(768 * 192 + 255) / 256, 256>>>(fc2_w,  wfc2_h,  wfc2_l,  768, 192);

    // 1) LN1 -> hi/lo
    ln_kernel<<<ROWS / 8, 256>>>(x, ln1_g, ln1_b, xln_h, xln_l);
    // 2) QKV: (ROWS,192) x (192,576) -> f32
    tc_gemm<0><<<dim3(3, ROWS / 128), 256, SMEM_G>>>(
        xln_h, xln_l, wqkv_h, wqkv_l, nullptr, nullptr, qkv, nullptr, nullptr, ROWS, 576, 192);
    // 3) attention -> hi/lo
    attn_kernel<<<dim3(BW, HEADS), 128>>>(qkv, btab, relidx, att_h, att_l);
    // 4) proj + bias + residual(x) -> x2 (f32)
    tc_gemm<EPI_BIAS | EPI_RESID><<<dim3(1, ROWS / 128), 256, SMEM_G>>>(
        att_h, att_l, wproj_h, wproj_l, proj_b, x, x2, nullptr, nullptr, ROWS, 192, 192);
    // 5) LN2 -> hi/lo
    ln_kernel<<<ROWS / 8, 256>>>(x2, ln2_g, ln2_b, xln_h, xln_l);
    // 6) fc1 + bias + gelu -> hid (hi/lo bf16)
    tc_gemm<EPI_BIAS | EPI_GELU | EPI_SPLIT><<<dim3(4, ROWS / 128), 256, SMEM_G>>>(
        xln_h, xln_l, wfc1_h, wfc1_l, fc1_b, nullptr, nullptr, hid_h, hid_l, ROWS, HIDDEN, 192);
    // 7) fc2 + bias + residual(x2) -> out (f32)
    tc_gemm<EPI_BIAS | EPI_RESID><<<dim3(1, ROWS / 128), 256, SMEM_G>>>(
        hid_h, hid_l, wfc2_h, wfc2_l, fc2_b, x2, out, nullptr, nullptr, ROWS, 192, HIDDEN);
}